// round 7
// baseline (speedup 1.0000x reference)
#include <cuda_runtime.h>
#include <cuda_fp16.h>
#include <math.h>

#define V_N 100000
#define E_N 1600000
#define MU_OVER_S 0.1125f

// ---------------- device scratch (static, no allocation) ----------------
__device__ __half P_buf[(size_t)V_N * 128];   // per-node fp16: [0:64) node proj, [64:128) neis proj
__device__ float  Q_buf[(size_t)V_N * 8];     // per-node W_rou projection
__device__ __half A_buf[(size_t)E_N * 64];    // per-edge transition matrices, dst-sorted order
__device__ float  Bsum_buf[(size_t)V_N * 8];  // per-node sum of edge biases
__device__ float  Hbuf[2 * (size_t)V_N * 8];  // ping-pong node state
__device__ int    cnt_buf[V_N];
__device__ int    offs_buf[V_N + 1];
__device__ int    cur_buf[V_N];
__device__ int    bsums_buf[256];             // scan block partials
__device__ int    src_sorted[E_N];
__device__ float  logits_buf[V_N];
__device__ float  blkmax_buf[256];
__device__ float  g_max;
__device__ float  g_acc[9];
__device__ int    g_idx64;

__device__ __forceinline__ float tanh_fast(float x) {
    float y;
    asm("tanh.approx.f32 %0, %1;" : "=f"(y) : "f"(x));
    return y;
}

// ---------------- index dtype detection (int64 vs int32) ----------------
__global__ void detect_kernel(const unsigned int* __restrict__ x) {
    if (threadIdx.x == 0 && blockIdx.x == 0) {
        int all0 = 1;
        for (int i = 1; i < 128; i += 2) all0 &= (x[i] == 0u);
        g_idx64 = all0;
    }
}

__device__ __forceinline__ int load_idx(const void* p, int e) {
    if (g_idx64) return (int)((const long long*)p)[e];
    return ((const int*)p)[e];
}

// ---------------- prep: zero counters + Bsum ----------------
__global__ void zero_prep_kernel() {
    int i = blockIdx.x * blockDim.x + threadIdx.x;
    if (i < V_N) cnt_buf[i] = 0;
    if (i < V_N * 8) Bsum_buf[i] = 0.f;
}

// ---------------- prep: histogram of dst ids ----------------
__global__ void count_kernel(const void* __restrict__ Xe) {
    int e = blockIdx.x * blockDim.x + threadIdx.x;
    if (e >= E_N) return;
    int draw = load_idx(Xe, e);   // raw 1-indexed, draw==V_N dropped
    if (draw < V_N) atomicAdd(&cnt_buf[draw], 1);
}

// ---------------- prep: 3-phase exclusive scan ----------------
__global__ void scan1_kernel() {
    __shared__ int sm[512];
    int i = blockIdx.x * 512 + threadIdx.x;
    int v = (i < V_N) ? cnt_buf[i] : 0;
    sm[threadIdx.x] = v;
    __syncthreads();
    for (int d = 1; d < 512; d <<= 1) {
        int t = (threadIdx.x >= d) ? sm[threadIdx.x - d] : 0;
        __syncthreads();
        sm[threadIdx.x] += t;
        __syncthreads();
    }
    if (i < V_N) offs_buf[i] = sm[threadIdx.x] - v;   // exclusive
    if (threadIdx.x == 511) bsums_buf[blockIdx.x] = sm[511];
}

__global__ void scan2_kernel(int nb) {
    __shared__ int sm[256];
    int v = (threadIdx.x < nb) ? bsums_buf[threadIdx.x] : 0;
    sm[threadIdx.x] = v;
    __syncthreads();
    for (int d = 1; d < 256; d <<= 1) {
        int t = (threadIdx.x >= d) ? sm[threadIdx.x - d] : 0;
        __syncthreads();
        sm[threadIdx.x] += t;
        __syncthreads();
    }
    if (threadIdx.x < nb) bsums_buf[threadIdx.x] = sm[threadIdx.x] - v;  // exclusive
}

__global__ void scan3_kernel() {
    int i = blockIdx.x * 512 + threadIdx.x;
    if (i < V_N) {
        int o = offs_buf[i] + bsums_buf[blockIdx.x];
        offs_buf[i] = o;
        cur_buf[i] = o;
        if (i == V_N - 1) offs_buf[V_N] = o + cnt_buf[i];
    }
}

// ---------------- per-node projection: P (fp16), Q ----------------
__global__ void proj_kernel(const float* __restrict__ feat,
                            const float* __restrict__ W_xi,
                            const float* __restrict__ W_rou) {
    __shared__ float2 Wn2[64 * 32];
    __shared__ float2 Wm2[64 * 32];
    __shared__ float  Wr[64 * 8];
    __shared__ float  xs[4][64];

    int tid = threadIdx.x;
    for (int idx = tid; idx < 2048; idx += blockDim.x) {
        int k = idx >> 5, l = idx & 31;
        Wn2[idx] = make_float2(W_xi[(2 * l) * 138 + k],      W_xi[(2 * l + 1) * 138 + k]);
        Wm2[idx] = make_float2(W_xi[(2 * l) * 138 + 64 + k], W_xi[(2 * l + 1) * 138 + 64 + k]);
    }
    for (int idx = tid; idx < 512; idx += blockDim.x) {
        int k = idx >> 3, s = idx & 7;
        Wr[idx] = W_rou[s * 64 + k];
    }
    __syncthreads();

    int w = tid >> 5, lane = tid & 31;
    int warpGlobal = blockIdx.x * 4 + w;
    int nWarps = gridDim.x * 4;
    for (int v = warpGlobal; v < V_N; v += nWarps) {
        xs[w][lane]      = feat[(size_t)v * 64 + lane];
        xs[w][32 + lane] = feat[(size_t)v * 64 + 32 + lane];
        __syncwarp();
        float2 an = make_float2(0.f, 0.f), am = make_float2(0.f, 0.f);
        float aq = 0.f;
#pragma unroll 8
        for (int k = 0; k < 64; k++) {
            float x = xs[w][k];
            float2 wn = Wn2[k * 32 + lane];
            float2 wm = Wm2[k * 32 + lane];
            an.x += x * wn.x; an.y += x * wn.y;
            am.x += x * wm.x; am.y += x * wm.y;
            if (lane < 8) aq += x * Wr[k * 8 + lane];
        }
        ((__half2*)(P_buf + (size_t)v * 128))[lane]      = __floats2half2_rn(an.x, an.y);
        ((__half2*)(P_buf + (size_t)v * 128 + 64))[lane] = __floats2half2_rn(am.x, am.y);
        if (lane < 8) Q_buf[(size_t)v * 8 + lane] = aq;
        __syncwarp();
    }
}

// ---------------- per-edge A precompute (writes dst-sorted), bias accumulate ----------------
__global__ void edge_pre_kernel(const void* __restrict__ Xn,
                                const void* __restrict__ Xe,
                                const int* __restrict__ etype,
                                const float* __restrict__ dg,
                                const float* __restrict__ W_xi,
                                const float* __restrict__ b_xi,
                                const float* __restrict__ b_rou) {
    __shared__ float4 Cet4[160];   // Cet[t][o] = W_xi[o][128+t] + b_xi[o]
    __shared__ float  brs[8];
    float* Cet = (float*)Cet4;
    int tid = threadIdx.x;
    for (int idx = tid; idx < 640; idx += blockDim.x) {
        int t = idx >> 6, o = idx & 63;
        Cet[idx] = W_xi[o * 138 + 128 + t] + b_xi[o];
    }
    if (tid < 8) brs[tid] = b_rou[tid];
    __syncthreads();

    long long gid = (long long)blockIdx.x * blockDim.x + tid;
    int e = (int)(gid >> 3), r = (int)(gid & 7);
    if (e >= E_N) return;

    int draw = load_idx(Xe, e);
    if (draw >= V_N) return;       // dropped edge: contributes nothing anywhere
    int de = draw - 1;

    int lane = tid & 31;
    int grp = lane >> 3;
    unsigned mask = 0xFFu << (grp * 8);

    int src = load_idx(Xn, e) - 1;
    int pos = 0;
    if (r == 0) {
        pos = atomicAdd(&cur_buf[draw], 1);
        src_sorted[pos] = src;
    }
    pos = __shfl_sync(mask, pos, grp * 8);

    int et = etype[e] - 1;
    float scale = MU_OVER_S / dg[e];

    uint4 p1r = *(const uint4*)(P_buf + (size_t)src * 128 + r * 8);
    uint4 p2r = *(const uint4*)(P_buf + (size_t)de * 128 + 64 + r * 8);
    const __half2* p1h = (const __half2*)&p1r;
    const __half2* p2h = (const __half2*)&p2r;
    const float4* c4 = (const float4*)(Cet + et * 64 + r * 8);
    float4 c0 = c4[0], c1 = c4[1];

    float2 pa0 = __half22float2(p1h[0]), pa1 = __half22float2(p1h[1]);
    float2 pa2 = __half22float2(p1h[2]), pa3 = __half22float2(p1h[3]);
    float2 pb0 = __half22float2(p2h[0]), pb1 = __half22float2(p2h[1]);
    float2 pb2 = __half22float2(p2h[2]), pb3 = __half22float2(p2h[3]);

    __half2 h[4];
    h[0] = __floats2half2_rn(tanh_fast(pa0.x + pb0.x + c0.x) * scale,
                             tanh_fast(pa0.y + pb0.y + c0.y) * scale);
    h[1] = __floats2half2_rn(tanh_fast(pa1.x + pb1.x + c0.z) * scale,
                             tanh_fast(pa1.y + pb1.y + c0.w) * scale);
    h[2] = __floats2half2_rn(tanh_fast(pa2.x + pb2.x + c1.x) * scale,
                             tanh_fast(pa2.y + pb2.y + c1.y) * scale);
    h[3] = __floats2half2_rn(tanh_fast(pa3.x + pb3.x + c1.z) * scale,
                             tanh_fast(pa3.y + pb3.y + c1.w) * scale);
    *(uint4*)(A_buf + (size_t)pos * 64 + r * 8) = *(const uint4*)h;

    float bval = tanhf(Q_buf[(size_t)de * 8 + r] + brs[r]);
    atomicAdd(&Bsum_buf[(size_t)draw * 8 + r], bval);
}

// ---------------- one recurrence step: warp per node, atomic-free ----------------
__global__ void step_kernel(const float* __restrict__ Hcur,
                            float* __restrict__ Hnext) {
    int gwarp = (blockIdx.x * blockDim.x + threadIdx.x) >> 5;
    int lane = threadIdx.x & 31;
    if (gwarp >= V_N) return;

    int beg = offs_buf[gwarp];
    int end = offs_buf[gwarp + 1];
    int eloc = lane >> 3, r = lane & 7;

    float acc = 0.f;
    for (int p = beg + eloc; p < end; p += 4) {
        int src = src_sorted[p];
        uint4 araw = *(const uint4*)(A_buf + (size_t)p * 64 + r * 8);
        const __half2* ah = (const __half2*)&araw;
        float2 a0 = __half22float2(ah[0]);
        float2 a1 = __half22float2(ah[1]);
        float2 a2 = __half22float2(ah[2]);
        float2 a3 = __half22float2(ah[3]);
        const float4* H4 = (const float4*)(Hcur + (size_t)src * 8);
        float4 h0 = H4[0], h1 = H4[1];
        acc += a0.x * h0.x + a0.y * h0.y + a1.x * h0.z + a1.y * h0.w
             + a2.x * h1.x + a2.y * h1.y + a3.x * h1.z + a3.y * h1.w;
    }
    acc += __shfl_xor_sync(0xFFFFFFFFu, acc, 8);
    acc += __shfl_xor_sync(0xFFFFFFFFu, acc, 16);
    if (lane < 8)
        Hnext[(size_t)gwarp * 8 + lane] = acc + Bsum_buf[(size_t)gwarp * 8 + lane];
}

// ---------------- readout ----------------
__global__ void logits_kernel(const float* __restrict__ H,
                              const float* __restrict__ W1,
                              const float* __restrict__ b1) {
    __shared__ float sm[256];
    __shared__ float w[8];
    int tid = threadIdx.x;
    if (tid < 8) w[tid] = W1[tid];
    __syncthreads();
    float bb = b1[0];
    float lmax = -1e30f;
    for (int v = blockIdx.x * blockDim.x + tid; v < V_N; v += gridDim.x * blockDim.x) {
        const float4* h4 = (const float4*)(H + (size_t)v * 8);
        float4 h0 = h4[0], h1 = h4[1];
        float l = h0.x * w[0] + h0.y * w[1] + h0.z * w[2] + h0.w * w[3]
                + h1.x * w[4] + h1.y * w[5] + h1.z * w[6] + h1.w * w[7] + bb;
        logits_buf[v] = l;
        lmax = fmaxf(lmax, l);
    }
    sm[tid] = lmax;
    __syncthreads();
    for (int s = 128; s; s >>= 1) {
        if (tid < s) sm[tid] = fmaxf(sm[tid], sm[tid + s]);
        __syncthreads();
    }
    if (tid == 0) blkmax_buf[blockIdx.x] = sm[0];
}

__global__ void reduce_max_kernel() {
    __shared__ float sm[256];
    int tid = threadIdx.x;
    sm[tid] = blkmax_buf[tid];
    __syncthreads();
    for (int s = 128; s; s >>= 1) {
        if (tid < s) sm[tid] = fmaxf(sm[tid], sm[tid + s]);
        __syncthreads();
    }
    if (tid == 0) g_max = sm[0];
    if (tid < 9) g_acc[tid] = 0.f;
}

__global__ void smacc_kernel(const float* __restrict__ H) {
    __shared__ float sm[256];
    int tid = threadIdx.x;
    float gm = g_max;
    float z = 0.f, s0 = 0.f, s1 = 0.f, s2 = 0.f, s3 = 0.f, s4 = 0.f, s5 = 0.f, s6 = 0.f, s7 = 0.f;
    for (int v = blockIdx.x * blockDim.x + tid; v < V_N; v += gridDim.x * blockDim.x) {
        float wv = expf(logits_buf[v] - gm);
        const float4* h4 = (const float4*)(H + (size_t)v * 8);
        float4 h0 = h4[0], h1 = h4[1];
        z += wv;
        s0 += wv * h0.x; s1 += wv * h0.y; s2 += wv * h0.z; s3 += wv * h0.w;
        s4 += wv * h1.x; s5 += wv * h1.y; s6 += wv * h1.z; s7 += wv * h1.w;
    }
    float vals[9] = {z, s0, s1, s2, s3, s4, s5, s6, s7};
#pragma unroll
    for (int j = 0; j < 9; j++) {
        sm[tid] = vals[j];
        __syncthreads();
        for (int s = 128; s; s >>= 1) {
            if (tid < s) sm[tid] += sm[tid + s];
            __syncthreads();
        }
        if (tid == 0) atomicAdd(&g_acc[j], sm[0]);
        __syncthreads();
    }
}

__global__ void final_kernel(float* __restrict__ out) {
    if (threadIdx.x < 8) out[threadIdx.x] = tanhf(g_acc[1 + threadIdx.x] / g_acc[0]);
}

// ---------------- launch ----------------
extern "C" void kernel_launch(void* const* d_in, const int* in_sizes, int n_in,
                              void* d_out, int out_size) {
    const float* feat  = (const float*)d_in[0];
    const void*  Xn    = d_in[1];
    const void*  Xe    = d_in[2];
    const int*   etype = (const int*)d_in[3];
    const float* dg    = (const float*)d_in[4];
    const float* Hinit = (const float*)d_in[5];
    const float* Wxi   = (const float*)d_in[6];
    const float* bxi   = (const float*)d_in[7];
    const float* Wrou  = (const float*)d_in[8];
    const float* brou  = (const float*)d_in[9];
    const float* W1    = (const float*)d_in[10];
    const float* b1    = (const float*)d_in[11];
    float* out = (float*)d_out;

    float* H;
    cudaGetSymbolAddress((void**)&H, Hbuf);
    float* H0 = H;
    float* H1 = H + (size_t)V_N * 8;

    const int EBLK  = (E_N * 8 + 255) / 256;          // edge_pre: 8 threads/edge
    const int CBLK  = (E_N + 255) / 256;              // count: 1 thread/edge
    const int SBLK  = (V_N + 511) / 512;              // scan blocks = 196
    const int ZBLK  = (V_N * 8 + 255) / 256;          // zero prep
    const int STBLK = (V_N + 7) / 8;                  // step: 8 warps/block, warp/node

    detect_kernel<<<1, 32>>>((const unsigned int*)Xn);
    zero_prep_kernel<<<ZBLK, 256>>>();
    count_kernel<<<CBLK, 256>>>(Xe);
    scan1_kernel<<<SBLK, 512>>>();
    scan2_kernel<<<1, 256>>>(SBLK);
    scan3_kernel<<<SBLK, 512>>>();
    proj_kernel<<<512, 128>>>(feat, Wxi, Wrou);
    edge_pre_kernel<<<EBLK, 256>>>(Xn, Xe, etype, dg, Wxi, bxi, brou);

    // T = 4 recurrence steps (ping-pong), no zeroing / atomics needed
    step_kernel<<<STBLK, 256>>>(Hinit, H0);
    step_kernel<<<STBLK, 256>>>(H0, H1);
    step_kernel<<<STBLK, 256>>>(H1, H0);
    step_kernel<<<STBLK, 256>>>(H0, H1);

    logits_kernel<<<256, 256>>>(H1, W1, b1);
    reduce_max_kernel<<<1, 256>>>();
    smacc_kernel<<<256, 256>>>(H1);
    final_kernel<<<1, 32>>>(out);
}

// round 8
// speedup vs baseline: 1.1704x; 1.1704x over previous
#include <cuda_runtime.h>
#include <cuda_fp16.h>
#include <math.h>

#define V_N 100000
#define E_N 1600000
#define MU_OVER_S 0.1125f

// ---------------- device scratch (static, no allocation) ----------------
__device__ __half      P_buf[(size_t)V_N * 128];  // per-node fp16: [0:64) node proj, [64:128) neis proj
__device__ float       Q_buf[(size_t)V_N * 8];    // per-node W_rou projection
__device__ signed char A8_buf[(size_t)E_N * 64];  // per-edge transition matrices, int8 (tanh*127)
__device__ float       s_buf[E_N];                // per-edge dequant scale = MU/S/(127*dg)
__device__ __half      B_buf[(size_t)E_N * 8];    // per-edge bias, fp16
__device__ int2        eidx_buf[E_N];             // per-edge (src0, raw dst)
__device__ float       Hsteps[4 * (size_t)V_N * 8]; // 4 step output buffers
__device__ float       logits_buf[V_N];
__device__ float       blkmax_buf[256];
__device__ float       g_max;
__device__ float       g_acc[9];
__device__ int         g_idx64;

__device__ __forceinline__ float tanh_fast(float x) {
    float y;
    asm("tanh.approx.f32 %0, %1;" : "=f"(y) : "f"(x));
    return y;
}

// ---------------- index dtype detection (int64 vs int32) ----------------
__global__ void detect_kernel(const unsigned int* __restrict__ x) {
    if (threadIdx.x == 0 && blockIdx.x == 0) {
        int all0 = 1;
        for (int i = 1; i < 128; i += 2) all0 &= (x[i] == 0u);
        g_idx64 = all0;
    }
}

__device__ __forceinline__ int load_idx(const void* p, int e) {
    if (g_idx64) return (int)((const long long*)p)[e];
    return ((const int*)p)[e];
}

// ---------------- zero all 4 step output buffers ----------------
__global__ void zero_all_kernel() {
    int i = blockIdx.x * blockDim.x + threadIdx.x;
    int n4 = 4 * V_N * 8 / 4;
    if (i < n4) ((float4*)Hsteps)[i] = make_float4(0.f, 0.f, 0.f, 0.f);
}

// ---------------- per-node projection: P (fp16), Q ----------------
__global__ void proj_kernel(const float* __restrict__ feat,
                            const float* __restrict__ W_xi,
                            const float* __restrict__ W_rou) {
    __shared__ float2 Wn2[64 * 32];  // Wn2[k*32+l] = (W_xi[2l][k], W_xi[2l+1][k])
    __shared__ float2 Wm2[64 * 32];  // same, k offset 64 (neis part)
    __shared__ float  Wr[64 * 8];    // Wr[k*8+s] = W_rou[s][k]
    __shared__ float  xs[4][64];

    int tid = threadIdx.x;
    for (int idx = tid; idx < 2048; idx += blockDim.x) {
        int k = idx >> 5, l = idx & 31;
        Wn2[idx] = make_float2(W_xi[(2 * l) * 138 + k],      W_xi[(2 * l + 1) * 138 + k]);
        Wm2[idx] = make_float2(W_xi[(2 * l) * 138 + 64 + k], W_xi[(2 * l + 1) * 138 + 64 + k]);
    }
    for (int idx = tid; idx < 512; idx += blockDim.x) {
        int k = idx >> 3, s = idx & 7;
        Wr[idx] = W_rou[s * 64 + k];
    }
    __syncthreads();

    int w = tid >> 5, lane = tid & 31;
    int warpGlobal = blockIdx.x * 4 + w;
    int nWarps = gridDim.x * 4;
    for (int v = warpGlobal; v < V_N; v += nWarps) {
        xs[w][lane]      = feat[(size_t)v * 64 + lane];
        xs[w][32 + lane] = feat[(size_t)v * 64 + 32 + lane];
        __syncwarp();
        float2 an = make_float2(0.f, 0.f), am = make_float2(0.f, 0.f);
        float aq = 0.f;
#pragma unroll 8
        for (int k = 0; k < 64; k++) {
            float x = xs[w][k];
            float2 wn = Wn2[k * 32 + lane];
            float2 wm = Wm2[k * 32 + lane];
            an.x += x * wn.x; an.y += x * wn.y;
            am.x += x * wm.x; am.y += x * wm.y;
            if (lane < 8) aq += x * Wr[k * 8 + lane];
        }
        ((__half2*)(P_buf + (size_t)v * 128))[lane]      = __floats2half2_rn(an.x, an.y);
        ((__half2*)(P_buf + (size_t)v * 128 + 64))[lane] = __floats2half2_rn(am.x, am.y);
        if (lane < 8) Q_buf[(size_t)v * 8 + lane] = aq;
        __syncwarp();
    }
}

// ---------------- per-edge precompute: A (int8), scale, bias, packed indices ----------------
// 8 threads per edge; thread r handles row r (8 A entries + 1 bias entry)
__global__ void edge_pre_kernel(const void* __restrict__ Xn,
                                const void* __restrict__ Xe,
                                const int* __restrict__ etype,
                                const float* __restrict__ dg,
                                const float* __restrict__ W_xi,
                                const float* __restrict__ b_xi,
                                const float* __restrict__ b_rou) {
    __shared__ float4 Cet4[160];   // Cet[t][o] = W_xi[o][128+t] + b_xi[o]
    __shared__ float  brs[8];
    float* Cet = (float*)Cet4;
    int tid = threadIdx.x;
    for (int idx = tid; idx < 640; idx += blockDim.x) {
        int t = idx >> 6, o = idx & 63;
        Cet[idx] = W_xi[o * 138 + 128 + t] + b_xi[o];
    }
    if (tid < 8) brs[tid] = b_rou[tid];
    __syncthreads();

    long long gid = (long long)blockIdx.x * blockDim.x + tid;
    int e = (int)(gid >> 3), r = (int)(gid & 7);
    if (e >= E_N) return;

    int src  = load_idx(Xn, e) - 1;
    int draw = load_idx(Xe, e);       // raw 1-indexed scatter id
    int de   = draw - 1;              // always valid for embedding gather
    int et   = etype[e] - 1;

    if (r == 0) {
        s_buf[e] = (MU_OVER_S / 127.0f) / dg[e];
        eidx_buf[e] = make_int2(src, draw);
    }

    uint4 p1r = *(const uint4*)(P_buf + (size_t)src * 128 + r * 8);
    uint4 p2r = *(const uint4*)(P_buf + (size_t)de * 128 + 64 + r * 8);
    const __half2* p1h = (const __half2*)&p1r;
    const __half2* p2h = (const __half2*)&p2r;
    const float4* c4 = (const float4*)(Cet + et * 64 + r * 8);
    float4 c0 = c4[0], c1 = c4[1];

    float2 pa0 = __half22float2(p1h[0]), pa1 = __half22float2(p1h[1]);
    float2 pa2 = __half22float2(p1h[2]), pa3 = __half22float2(p1h[3]);
    float2 pb0 = __half22float2(p2h[0]), pb1 = __half22float2(p2h[1]);
    float2 pb2 = __half22float2(p2h[2]), pb3 = __half22float2(p2h[3]);

    float t0 = tanh_fast(pa0.x + pb0.x + c0.x);
    float t1 = tanh_fast(pa0.y + pb0.y + c0.y);
    float t2 = tanh_fast(pa1.x + pb1.x + c0.z);
    float t3 = tanh_fast(pa1.y + pb1.y + c0.w);
    float t4 = tanh_fast(pa2.x + pb2.x + c1.x);
    float t5 = tanh_fast(pa2.y + pb2.y + c1.y);
    float t6 = tanh_fast(pa3.x + pb3.x + c1.z);
    float t7 = tanh_fast(pa3.y + pb3.y + c1.w);

    // quantize to int8 (|t|<1 so rint(t*127) fits in [-127,127])
    uint2 q;
    {
        int i0 = __float2int_rn(t0 * 127.f), i1 = __float2int_rn(t1 * 127.f);
        int i2 = __float2int_rn(t2 * 127.f), i3 = __float2int_rn(t3 * 127.f);
        int i4 = __float2int_rn(t4 * 127.f), i5 = __float2int_rn(t5 * 127.f);
        int i6 = __float2int_rn(t6 * 127.f), i7 = __float2int_rn(t7 * 127.f);
        q.x = (i0 & 0xFF) | ((i1 & 0xFF) << 8) | ((i2 & 0xFF) << 16) | ((i3 & 0xFF) << 24);
        q.y = (i4 & 0xFF) | ((i5 & 0xFF) << 8) | ((i6 & 0xFF) << 16) | ((i7 & 0xFF) << 24);
    }
    *(uint2*)(A8_buf + (size_t)e * 64 + r * 8) = q;

    B_buf[(size_t)e * 8 + r] = __float2half_rn(tanh_fast(Q_buf[(size_t)de * 8 + r] + brs[r]));
}

// ---------------- one recurrence step (scatter-atomic, int8 A) ----------------
__global__ void step_kernel(const float* __restrict__ Hcur,
                            float* __restrict__ Hnext) {
    long long gid = (long long)blockIdx.x * blockDim.x + threadIdx.x;
    int e = (int)(gid >> 3), r = (int)(gid & 7);
    if (e >= E_N) return;

    int2 idx = eidx_buf[e];
    uint2 q = *(const uint2*)(A8_buf + (size_t)e * 64 + r * 8);
    const signed char* qc = (const signed char*)&q;

    const float4* H4 = (const float4*)(Hcur + (size_t)idx.x * 8);
    float4 h0 = H4[0], h1 = H4[1];

    float sum = (float)qc[0] * h0.x + (float)qc[1] * h0.y
              + (float)qc[2] * h0.z + (float)qc[3] * h0.w
              + (float)qc[4] * h1.x + (float)qc[5] * h1.y
              + (float)qc[6] * h1.z + (float)qc[7] * h1.w;

    float out = s_buf[e] * sum + __half2float(B_buf[(size_t)e * 8 + r]);

    if (idx.y < V_N) atomicAdd(&Hnext[(size_t)idx.y * 8 + r], out);
}

// ---------------- readout ----------------
__global__ void logits_kernel(const float* __restrict__ H,
                              const float* __restrict__ W1,
                              const float* __restrict__ b1) {
    __shared__ float sm[256];
    __shared__ float w[8];
    int tid = threadIdx.x;
    if (tid < 8) w[tid] = W1[tid];
    __syncthreads();
    float bb = b1[0];
    float lmax = -1e30f;
    for (int v = blockIdx.x * blockDim.x + tid; v < V_N; v += gridDim.x * blockDim.x) {
        const float4* h4 = (const float4*)(H + (size_t)v * 8);
        float4 h0 = h4[0], h1 = h4[1];
        float l = h0.x * w[0] + h0.y * w[1] + h0.z * w[2] + h0.w * w[3]
                + h1.x * w[4] + h1.y * w[5] + h1.z * w[6] + h1.w * w[7] + bb;
        logits_buf[v] = l;
        lmax = fmaxf(lmax, l);
    }
    sm[tid] = lmax;
    __syncthreads();
    for (int s = 128; s; s >>= 1) {
        if (tid < s) sm[tid] = fmaxf(sm[tid], sm[tid + s]);
        __syncthreads();
    }
    if (tid == 0) blkmax_buf[blockIdx.x] = sm[0];
}

__global__ void reduce_max_kernel() {
    __shared__ float sm[256];
    int tid = threadIdx.x;
    sm[tid] = blkmax_buf[tid];
    __syncthreads();
    for (int s = 128; s; s >>= 1) {
        if (tid < s) sm[tid] = fmaxf(sm[tid], sm[tid + s]);
        __syncthreads();
    }
    if (tid == 0) g_max = sm[0];
    if (tid < 9) g_acc[tid] = 0.f;
}

__global__ void smacc_kernel(const float* __restrict__ H) {
    __shared__ float sm[256];
    int tid = threadIdx.x;
    float gm = g_max;
    float z = 0.f, s0 = 0.f, s1 = 0.f, s2 = 0.f, s3 = 0.f, s4 = 0.f, s5 = 0.f, s6 = 0.f, s7 = 0.f;
    for (int v = blockIdx.x * blockDim.x + tid; v < V_N; v += gridDim.x * blockDim.x) {
        float wv = expf(logits_buf[v] - gm);
        const float4* h4 = (const float4*)(H + (size_t)v * 8);
        float4 h0 = h4[0], h1 = h4[1];
        z += wv;
        s0 += wv * h0.x; s1 += wv * h0.y; s2 += wv * h0.z; s3 += wv * h0.w;
        s4 += wv * h1.x; s5 += wv * h1.y; s6 += wv * h1.z; s7 += wv * h1.w;
    }
    float vals[9] = {z, s0, s1, s2, s3, s4, s5, s6, s7};
#pragma unroll
    for (int j = 0; j < 9; j++) {
        sm[tid] = vals[j];
        __syncthreads();
        for (int s = 128; s; s >>= 1) {
            if (tid < s) sm[tid] += sm[tid + s];
            __syncthreads();
        }
        if (tid == 0) atomicAdd(&g_acc[j], sm[0]);
        __syncthreads();
    }
}

__global__ void final_kernel(float* __restrict__ out) {
    if (threadIdx.x < 8) out[threadIdx.x] = tanhf(g_acc[1 + threadIdx.x] / g_acc[0]);
}

// ---------------- launch ----------------
extern "C" void kernel_launch(void* const* d_in, const int* in_sizes, int n_in,
                              void* d_out, int out_size) {
    const float* feat  = (const float*)d_in[0];
    const void*  Xn    = d_in[1];
    const void*  Xe    = d_in[2];
    const int*   etype = (const int*)d_in[3];
    const float* dg    = (const float*)d_in[4];
    const float* Hinit = (const float*)d_in[5];
    const float* Wxi   = (const float*)d_in[6];
    const float* bxi   = (const float*)d_in[7];
    const float* Wrou  = (const float*)d_in[8];
    const float* brou  = (const float*)d_in[9];
    const float* W1    = (const float*)d_in[10];
    const float* b1    = (const float*)d_in[11];
    float* out = (float*)d_out;

    float* H;
    cudaGetSymbolAddress((void**)&H, Hsteps);
    float* HA = H;
    float* HB = H + 1 * (size_t)V_N * 8;
    float* HC = H + 2 * (size_t)V_N * 8;
    float* HD = H + 3 * (size_t)V_N * 8;

    const int EBLK = (E_N * 8 + 255) / 256;            // 50000 blocks, 8 threads/edge
    const int ZBLK = (4 * V_N * 8 / 4 + 255) / 256;    // zero all 4 H buffers

    detect_kernel<<<1, 32>>>((const unsigned int*)Xn);
    zero_all_kernel<<<ZBLK, 256>>>();
    proj_kernel<<<512, 128>>>(feat, Wxi, Wrou);
    edge_pre_kernel<<<EBLK, 256>>>(Xn, Xe, etype, dg, Wxi, bxi, brou);

    // T = 4 recurrence steps into pre-zeroed buffers
    step_kernel<<<EBLK, 256>>>(Hinit, HA);
    step_kernel<<<EBLK, 256>>>(HA, HB);
    step_kernel<<<EBLK, 256>>>(HB, HC);
    step_kernel<<<EBLK, 256>>>(HC, HD);

    logits_kernel<<<256, 256>>>(HD, W1, b1);
    reduce_max_kernel<<<1, 256>>>();
    smacc_kernel<<<256, 256>>>(HD);
    final_kernel<<<1, 32>>>(out);
}